// round 17
// baseline (speedup 1.0000x reference)
#include <cuda_runtime.h>
#include <cuda_bf16.h>
#include <cuda_fp16.h>
#include <math.h>
#include <stdint.h>

#define NN 50000
#define NE 800000
#define MPAD 50048   // 391 * 128

// ---------------- device scratch (allocation-free) ----------------
__device__ float g_buf1[NN * 512];          // Y1 / Y3 (fp16 alias)
__device__ float g_buf2[NN * 512];          // Y2 (fp16 alias) / Ahd + heads T
__device__ __half g_Ah[(size_t)MPAD * 512]; // fp16 activations (GEMM A operand)
__device__ __half g_Bt1[512 * 512];         // fp16 weights, N-major rows, K-contig
__device__ __half g_Bt2[512 * 512];
__device__ __half g_Bt3[256 * 512];
__device__ __half g_Whd[128 * 512];         // heads B: [hi 256 | lo 256], rows>=72 zero
__device__ float g_dis[NN];
__device__ int   g_indeg[NN];
__device__ int   g_rowptr[NN + 1];
__device__ int   g_cursor[NN];
__device__ int2  g_colval[NE];              // (col, val bits)
__device__ float g_ball[72];
__device__ int   g_blocksum[64];

// ---------------- helpers ----------------
__device__ __forceinline__ uint32_t smem_u32(const void* p) {
    uint32_t a;
    asm("{ .reg .u64 t; cvta.to.shared.u64 t, %1; cvt.u32.u64 %0, t; }" : "=r"(a) : "l"(p));
    return a;
}
__device__ __forceinline__ void ldsm4(uint32_t* r, uint32_t addr) {
    asm volatile("ldmatrix.sync.aligned.m8n8.x4.shared.b16 {%0,%1,%2,%3}, [%4];"
                 : "=r"(r[0]), "=r"(r[1]), "=r"(r[2]), "=r"(r[3]) : "r"(addr));
}
__device__ __forceinline__ void mma16816(float* c, const uint32_t* a, const uint32_t* b) {
    asm volatile("mma.sync.aligned.m16n8k16.row.col.f32.f16.f16.f32 "
                 "{%0,%1,%2,%3}, {%4,%5,%6,%7}, {%8,%9}, {%0,%1,%2,%3};"
                 : "+f"(c[0]), "+f"(c[1]), "+f"(c[2]), "+f"(c[3])
                 : "r"(a[0]), "r"(a[1]), "r"(a[2]), "r"(a[3]), "r"(b[0]), "r"(b[1]));
}
#define CP_ASYNC16(dst, src) \
    asm volatile("cp.async.cg.shared.global [%0], [%1], 16;" :: "r"(dst), "l"(src))
#define CP_COMMIT() asm volatile("cp.async.commit_group;" ::: "memory")
#define CP_WAIT2()  asm volatile("cp.async.wait_group 2;" ::: "memory")

// ---------------- CSR build ----------------
__global__ void zero_indeg_kernel() {
    int i = blockIdx.x * blockDim.x + threadIdx.x;
    if (i < NN) g_indeg[i] = 0;
}
__global__ void count_kernel(const int* __restrict__ dst) {
    int e = blockIdx.x * blockDim.x + threadIdx.x;
    if (e < NE) atomicAdd(&g_indeg[dst[e]], 1);
}
// block sums + fused dis computation
__global__ void scan_part1() {
    __shared__ int ws[32];
    int i = blockIdx.x * 1024 + threadIdx.x;
    int v = (i < NN) ? g_indeg[i] : 0;
    if (i < NN) g_dis[i] = rsqrtf((float)(v + 1));
    int s = v;
    #pragma unroll
    for (int o = 16; o > 0; o >>= 1) s += __shfl_down_sync(0xffffffffu, s, o);
    if ((threadIdx.x & 31) == 0) ws[threadIdx.x >> 5] = s;
    __syncthreads();
    if (threadIdx.x < 32) {
        int t = ws[threadIdx.x];
        #pragma unroll
        for (int o = 16; o > 0; o >>= 1) t += __shfl_down_sync(0xffffffffu, t, o);
        if (threadIdx.x == 0) g_blocksum[blockIdx.x] = t;
    }
}
__global__ void scan_part2() {
    int acc = 0;
    for (int b = 0; b < 49; ++b) { int t = g_blocksum[b]; g_blocksum[b] = acc; acc += t; }
    g_rowptr[NN] = acc;
}
__global__ void scan_part3() {
    __shared__ int ws[32];
    int tid = threadIdx.x;
    int i = blockIdx.x * 1024 + tid;
    int v = (i < NN) ? g_indeg[i] : 0;
    int x = v;
    #pragma unroll
    for (int o = 1; o < 32; o <<= 1) {
        int t = __shfl_up_sync(0xffffffffu, x, o);
        if ((tid & 31) >= o) x += t;
    }
    if ((tid & 31) == 31) ws[tid >> 5] = x;
    __syncthreads();
    if (tid < 32) {
        int s = ws[tid];
        #pragma unroll
        for (int o = 1; o < 32; o <<= 1) {
            int t = __shfl_up_sync(0xffffffffu, s, o);
            if (tid >= o) s += t;
        }
        ws[tid] = s;
    }
    __syncthreads();
    int wofs = (tid >= 32) ? ws[(tid >> 5) - 1] : 0;
    int excl = x + wofs - v + g_blocksum[blockIdx.x];
    if (i < NN) { g_rowptr[i] = excl; g_cursor[i] = excl; }
}
__global__ void scatter_kernel(const int* __restrict__ src, const int* __restrict__ dst) {
    int e = blockIdx.x * blockDim.x + threadIdx.x;
    if (e < NE) {
        int s = src[e], d = dst[e];
        int p = atomicAdd(&g_cursor[d], 1);
        g_colval[p] = make_int2(s, __float_as_int(g_dis[s] * g_dis[d]));
    }
}

// ---------------- conversions ----------------
// x f32 [NN,512] -> fp16 [MPAD,512], pad rows zero
__global__ void convert_x_kernel(const float* __restrict__ X) {
    int idx = blockIdx.x * 256 + threadIdx.x;
    if (idx >= MPAD * 128) return;
    int row = idx >> 7, col = (idx & 127) << 2;
    uint2 o = make_uint2(0, 0);
    if (row < NN) {
        float4 v = *(const float4*)(X + (size_t)row * 512 + col);
        __half2 h0 = __floats2half2_rn(v.x, v.y);
        __half2 h1 = __floats2half2_rn(v.z, v.w);
        o.x = *(uint32_t*)&h0; o.y = *(uint32_t*)&h1;
    }
    *(uint2*)(g_Ah + (size_t)row * 512 + col) = o;
}

// W [K=512][N] f32 -> Bt [N][512] fp16, N-major rows
__global__ void convert_B_kernel(const float* __restrict__ W, __half* __restrict__ Bt, int N) {
    int idx = blockIdx.x * 256 + threadIdx.x;
    if (idx >= 512 * N) return;
    int k = idx / N, n = idx % N;
    Bt[(size_t)n * 512 + k] = __float2half_rn(W[idx]);
}

// heads weights -> g_Whd [128 rows][512] fp16 split ([hi 256|lo 256]); rows >= 72 zero. + g_ball
__global__ void pack_heads_kernel(
    const float* __restrict__ We, const float* __restrict__ be,
    const float* __restrict__ Wh, const float* __restrict__ bh,
    const float* __restrict__ Wg, const float* __restrict__ bg) {
    int idx = blockIdx.x * blockDim.x + threadIdx.x;
    if (idx < 128 * 256) {
        int n = idx >> 8, k = idx & 255;
        float v = 0.f;
        if (n < 7) v = We[k * 7 + n];
        else if (n < 15) v = Wh[k * 8 + (n - 7)];
        else if (n < 72) v = Wg[k * 57 + (n - 15)];
        __half hi = __float2half_rn(v);
        float l = v - __half2float(hi);
        g_Whd[n * 512 + k] = hi;
        g_Whd[n * 512 + 256 + k] = __float2half_rn(l);
    }
    if (idx < 72) {
        float v;
        if (idx < 7) v = be[idx];
        else if (idx < 15) v = bh[idx - 7];
        else v = bg[idx - 15];
        g_ball[idx] = v;
    }
}

// ---------------- mma.sync GEMM: C[M,N] = A @ B^T (fp16, fp32 accum) ----
// A: [M, TERMK] fp16. B: [N, NTERMS*TERMK] fp16 (NTERMS=2 => residual split summed).
// NTERMS*TERMK/32 K-stages of 32. CTA 128x128, 8 warps of 64x32. 4-stage cp.async.
// m0 = row offset of this launch's m-chunk.
#define SROW 40
#define STG_BYTES (128 * SROW * 2)   // 10240 B per tile per stage
template <int TERMK, int NTERMS, typename OutT>
__global__ __launch_bounds__(256) void gemm_mma_kernel(
    const __half* __restrict__ A, const __half* __restrict__ Bt,
    OutT* __restrict__ C, int M, int N, int m0)
{
    extern __shared__ __align__(16) __half dsmem[];
    const uint32_t as_u32 = smem_u32(dsmem);
    const uint32_t bs_u32 = as_u32 + 4 * STG_BYTES;

    constexpr int NSTG = NTERMS * TERMK / 32;
    constexpr int TPS = TERMK / 32;      // stages per term
    constexpr int BRS = NTERMS * TERMK;  // B row stride (elems)

    const int tid = threadIdx.x;
    const int wid = tid >> 5, lane = tid & 31;
    const int bm = m0 + blockIdx.y * 128;
    const int bn = blockIdx.x * 128;
    const int warp_m = (wid >> 2) * 64;
    const int warp_n = (wid & 3) * 32;

    const int lrow = tid >> 2;
    const int lseg = (tid & 3) << 3;

    auto gload_async = [&](int s) {
        int term = s / TPS, kk = (s % TPS) << 5;
        int bc = term * TERMK + kk;
        uint32_t ab = as_u32 + (uint32_t)(s & 3) * STG_BYTES;
        uint32_t bb = bs_u32 + (uint32_t)(s & 3) * STG_BYTES;
        #pragma unroll
        for (int i = 0; i < 2; ++i) {
            int row = lrow + i * 64;
            const __half* pa = A + (size_t)(bm + row) * TERMK + kk + lseg;
            const __half* pb = Bt + (size_t)(bn + row) * BRS + bc + lseg;
            uint32_t off = (uint32_t)(row * SROW + lseg) * 2;
            CP_ASYNC16(ab + off, pa);
            CP_ASYNC16(bb + off, pb);
        }
    };

    float acc[4][4][4];
    #pragma unroll
    for (int mi = 0; mi < 4; mi++)
        #pragma unroll
        for (int ni = 0; ni < 4; ni++)
            #pragma unroll
            for (int j = 0; j < 4; j++) acc[mi][ni][j] = 0.f;

    const uint32_t a_lm = as_u32 + (uint32_t)(warp_m + (lane & 15)) * (SROW * 2) + ((lane >> 4) << 4);
    const int bq = lane >> 3;
    const uint32_t b_lm = bs_u32 + (uint32_t)(warp_n + ((bq >> 1) << 3) + (lane & 7)) * (SROW * 2)
                          + ((bq & 1) << 4);

    auto compute = [&](int bi) {
        uint32_t soff = (uint32_t)bi * STG_BYTES;
        #pragma unroll
        for (int ks = 0; ks < 2; ++ks) {
            uint32_t a[4][4], b[4][2];
            #pragma unroll
            for (int mi = 0; mi < 4; mi++)
                ldsm4(a[mi], a_lm + soff + (uint32_t)mi * 16 * (SROW * 2) + ks * 32);
            #pragma unroll
            for (int nb = 0; nb < 2; nb++) {
                uint32_t r[4];
                ldsm4(r, b_lm + soff + (uint32_t)nb * 16 * (SROW * 2) + ks * 32);
                b[nb * 2][0] = r[0]; b[nb * 2][1] = r[1];
                b[nb * 2 + 1][0] = r[2]; b[nb * 2 + 1][1] = r[3];
            }
            #pragma unroll
            for (int mi = 0; mi < 4; mi++)
                #pragma unroll
                for (int ni = 0; ni < 4; ni++)
                    mma16816(acc[mi][ni], a[mi], b[ni]);
        }
    };

    gload_async(0); CP_COMMIT();
    gload_async(1); CP_COMMIT();
    gload_async(2); CP_COMMIT();

    for (int s = 0; s < NSTG; ++s) {
        CP_WAIT2();
        __syncthreads();
        if (s + 3 < NSTG) gload_async(s + 3);
        CP_COMMIT();
        compute(s & 3);
    }

    #pragma unroll
    for (int mi = 0; mi < 4; mi++) {
        int row0 = bm + warp_m + mi * 16 + (lane >> 2);
        #pragma unroll
        for (int ni = 0; ni < 4; ni++) {
            int col = bn + warp_n + ni * 8 + ((lane & 3) << 1);
            #pragma unroll
            for (int half_ = 0; half_ < 2; ++half_) {
                int r = row0 + half_ * 8;
                if (r < M) {
                    float v0 = acc[mi][ni][half_ * 2 + 0];
                    float v1 = acc[mi][ni][half_ * 2 + 1];
                    if (sizeof(OutT) == 4) {
                        *(float2*)&(((float*)C)[(size_t)r * N + col]) = make_float2(v0, v1);
                    } else {
                        __half2 h = __floats2half2_rn(v0, v1);
                        *(__half2*)&(((__half*)C)[(size_t)r * N + col]) = h;
                    }
                }
            }
        }
    }
}

// ---------------- aggregation (hidden layers, fp16 gather, D=512) ----------------
// h = relu(bias + dis^2*Y[i] + sum val*Y[col]); writes fp16 into g_Ah. Chunked by node_base.
__global__ __launch_bounds__(256) void aggregate_h_kernel(
    const __half* __restrict__ Y, const float* __restrict__ bias, int node_base) {
    int gt = blockIdx.x * 256 + threadIdx.x;
    int node = node_base + (gt >> 6);   // 64 threads/node
    int lane = gt & 63;
    if (node >= NN) return;
    int c = lane << 3;                  // 8 elems/thread

    float acc[8];
    float dv = g_dis[node];
    float w = dv * dv;
    {
        float4 b0 = *(const float4*)(bias + c);
        float4 b1 = *(const float4*)(bias + c + 4);
        uint4 raw = *(const uint4*)(Y + (size_t)node * 512 + c);
        const __half2* h = (const __half2*)&raw;
        float2 f0 = __half22float2(h[0]), f1 = __half22float2(h[1]);
        float2 f2 = __half22float2(h[2]), f3 = __half22float2(h[3]);
        acc[0] = fmaf(w, f0.x, b0.x); acc[1] = fmaf(w, f0.y, b0.y);
        acc[2] = fmaf(w, f1.x, b0.z); acc[3] = fmaf(w, f1.y, b0.w);
        acc[4] = fmaf(w, f2.x, b1.x); acc[5] = fmaf(w, f2.y, b1.y);
        acc[6] = fmaf(w, f3.x, b1.z); acc[7] = fmaf(w, f3.y, b1.w);
    }

    int e0 = g_rowptr[node], e1 = g_rowptr[node + 1];
    int p = e0;
    for (; p + 2 <= e1; p += 2) {
        int2 cv0 = __ldg(&g_colval[p + 0]);
        int2 cv1 = __ldg(&g_colval[p + 1]);
        uint4 r0 = *(const uint4*)(Y + (size_t)cv0.x * 512 + c);
        uint4 r1 = *(const uint4*)(Y + (size_t)cv1.x * 512 + c);
        float v0 = __int_as_float(cv0.y), v1 = __int_as_float(cv1.y);
        const __half2* h0 = (const __half2*)&r0;
        const __half2* h1 = (const __half2*)&r1;
        #pragma unroll
        for (int q = 0; q < 4; ++q) {
            float2 f0 = __half22float2(h0[q]);
            float2 f1 = __half22float2(h1[q]);
            acc[q * 2 + 0] = fmaf(v0, f0.x, acc[q * 2 + 0]);
            acc[q * 2 + 1] = fmaf(v0, f0.y, acc[q * 2 + 1]);
            acc[q * 2 + 0] = fmaf(v1, f1.x, acc[q * 2 + 0]);
            acc[q * 2 + 1] = fmaf(v1, f1.y, acc[q * 2 + 1]);
        }
    }
    for (; p < e1; ++p) {
        int2 cv = __ldg(&g_colval[p]);
        float v = __int_as_float(cv.y);
        uint4 r = *(const uint4*)(Y + (size_t)cv.x * 512 + c);
        const __half2* h = (const __half2*)&r;
        #pragma unroll
        for (int q = 0; q < 4; ++q) {
            float2 f = __half22float2(h[q]);
            acc[q * 2 + 0] = fmaf(v, f.x, acc[q * 2 + 0]);
            acc[q * 2 + 1] = fmaf(v, f.y, acc[q * 2 + 1]);
        }
    }
    uint4 o;
    __half2 h0 = __floats2half2_rn(fmaxf(acc[0], 0.f), fmaxf(acc[1], 0.f));
    __half2 h1 = __floats2half2_rn(fmaxf(acc[2], 0.f), fmaxf(acc[3], 0.f));
    __half2 h2 = __floats2half2_rn(fmaxf(acc[4], 0.f), fmaxf(acc[5], 0.f));
    __half2 h3 = __floats2half2_rn(fmaxf(acc[6], 0.f), fmaxf(acc[7], 0.f));
    o.x = *(uint32_t*)&h0; o.y = *(uint32_t*)&h1;
    o.z = *(uint32_t*)&h2; o.w = *(uint32_t*)&h3;
    *(uint4*)(g_Ah + (size_t)node * 512 + c) = o;
}

// ---------------- layer-3 aggregation (fp16 gather, D=256) -> emb f32 + heads fp16 ----------------
__global__ __launch_bounds__(256) void aggregate3_kernel(
    const __half* __restrict__ Y, float* __restrict__ emb, const float* __restrict__ bias,
    __half* __restrict__ Ahd, int node_base) {
    int gt = blockIdx.x * 256 + threadIdx.x;
    int node = node_base + (gt >> 5);   // 32 threads/node
    int lane = gt & 31;
    if (node >= MPAD) return;
    int c = lane << 3;                  // 8 elems/thread
    if (node >= NN) {                   // zero heads-A padding rows
        *(uint4*)(Ahd + (size_t)node * 256 + c) = make_uint4(0, 0, 0, 0);
        return;
    }

    float acc[8];
    float dv = g_dis[node];
    float w = dv * dv;
    {
        float4 b0 = *(const float4*)(bias + c);
        float4 b1 = *(const float4*)(bias + c + 4);
        uint4 raw = *(const uint4*)(Y + (size_t)node * 256 + c);
        const __half2* h = (const __half2*)&raw;
        float2 f0 = __half22float2(h[0]), f1 = __half22float2(h[1]);
        float2 f2 = __half22float2(h[2]), f3 = __half22float2(h[3]);
        acc[0] = fmaf(w, f0.x, b0.x); acc[1] = fmaf(w, f0.y, b0.y);
        acc[2] = fmaf(w, f1.x, b0.z); acc[3] = fmaf(w, f1.y, b0.w);
        acc[4] = fmaf(w, f2.x, b1.x); acc[5] = fmaf(w, f2.y, b1.y);
        acc[6] = fmaf(w, f3.x, b1.z); acc[7] = fmaf(w, f3.y, b1.w);
    }

    int e0 = g_rowptr[node], e1 = g_rowptr[node + 1];
    for (int p = e0; p < e1; ++p) {
        int2 cv = __ldg(&g_colval[p]);
        float v = __int_as_float(cv.y);
        uint4 r = *(const uint4*)(Y + (size_t)cv.x * 256 + c);
        const __half2* h = (const __half2*)&r;
        #pragma unroll
        for (int q = 0; q < 4; ++q) {
            float2 f = __half22float2(h[q]);
            acc[q * 2 + 0] = fmaf(v, f.x, acc[q * 2 + 0]);
            acc[q * 2 + 1] = fmaf(v, f.y, acc[q * 2 + 1]);
        }
    }
    *(float4*)(emb + (size_t)node * 256 + c) =
        make_float4(acc[0], acc[1], acc[2], acc[3]);
    *(float4*)(emb + (size_t)node * 256 + c + 4) =
        make_float4(acc[4], acc[5], acc[6], acc[7]);
    uint4 o;
    __half2 h0 = __floats2half2_rn(acc[0], acc[1]);
    __half2 h1 = __floats2half2_rn(acc[2], acc[3]);
    __half2 h2 = __floats2half2_rn(acc[4], acc[5]);
    __half2 h3 = __floats2half2_rn(acc[6], acc[7]);
    o.x = *(uint32_t*)&h0; o.y = *(uint32_t*)&h1;
    o.z = *(uint32_t*)&h2; o.w = *(uint32_t*)&h3;
    *(uint4*)(Ahd + (size_t)node * 256 + c) = o;
}

// ---------------- head output split (adds bias) ----------------
__global__ void split_heads_kernel(const float* __restrict__ T,
                                   float* __restrict__ outE,
                                   float* __restrict__ outH,
                                   float* __restrict__ outG) {
    int idx = blockIdx.x * blockDim.x + threadIdx.x;
    if (idx >= NN * 72) return;
    int i = idx / 72, j = idx % 72;
    float v = T[(size_t)i * 128 + j] + g_ball[j];
    if (j < 7) outE[i * 7 + j] = v;
    else if (j < 15) outH[i * 8 + (j - 7)] = v;
    else outG[i * 57 + (j - 15)] = v;
}

// ---------------- launch ----------------
extern "C" void kernel_launch(void* const* d_in, const int* in_sizes, int n_in,
                              void* d_out, int out_size) {
    const float* x  = (const float*)d_in[0];
    const int*   ei = (const int*)d_in[1];
    const float* W1 = (const float*)d_in[2];
    const float* b1 = (const float*)d_in[3];
    const float* W2 = (const float*)d_in[4];
    const float* b2 = (const float*)d_in[5];
    const float* W3 = (const float*)d_in[6];
    const float* b3 = (const float*)d_in[7];
    const float* We = (const float*)d_in[8];
    const float* be = (const float*)d_in[9];
    const float* Wh = (const float*)d_in[10];
    const float* bh = (const float*)d_in[11];
    const float* Wg = (const float*)d_in[12];
    const float* bg = (const float*)d_in[13];

    const int* srcArr = ei;
    const int* dstArr = ei + NE;

    float* out  = (float*)d_out;
    float* emb  = out;
    float* outE = out + (size_t)NN * 256;
    float* outH = outE + (size_t)NN * 7;
    float* outG = outH + (size_t)NN * 8;

    float *buf1, *buf2;
    __half *Ah, *Bt1, *Bt2, *Bt3, *Whd;
    cudaGetSymbolAddress((void**)&buf1, g_buf1);
    cudaGetSymbolAddress((void**)&buf2, g_buf2);
    cudaGetSymbolAddress((void**)&Ah,  g_Ah);
    cudaGetSymbolAddress((void**)&Bt1, g_Bt1);
    cudaGetSymbolAddress((void**)&Bt2, g_Bt2);
    cudaGetSymbolAddress((void**)&Bt3, g_Bt3);
    cudaGetSymbolAddress((void**)&Whd, g_Whd);

    const int GEMM_SMEM = 8 * STG_BYTES;  // 81920 B
    cudaFuncSetAttribute(gemm_mma_kernel<512, 1, __half>, cudaFuncAttributeMaxDynamicSharedMemorySize, GEMM_SMEM);
    cudaFuncSetAttribute(gemm_mma_kernel<256, 2, float>,  cudaFuncAttributeMaxDynamicSharedMemorySize, GEMM_SMEM);

    // side stream + events (created once, eagerly; host-side objects only)
    static cudaStream_t s2 = nullptr;
    static cudaEvent_t ev[17];
    if (s2 == nullptr) {
        cudaStreamCreateWithFlags(&s2, cudaStreamNonBlocking);
        for (int i = 0; i < 17; ++i) cudaEventCreateWithFlags(&ev[i], cudaEventDisableTiming);
    }
    cudaEvent_t evFork = ev[0], evCSR = ev[1];
    cudaEvent_t* aEv = &ev[2];
    cudaEvent_t evG2 = ev[6];
    cudaEvent_t* bEv = &ev[7];
    cudaEvent_t evG3 = ev[11];
    cudaEvent_t* cEv = &ev[12];
    cudaEvent_t evTail = ev[16];

    // m-chunking: 391 blocks -> {98,98,98,97}; node bases multiples of 128
    static const int CB[4]   = {98, 98, 98, 97};
    static const int NB[4]   = {0, 12544, 25088, 37632};
    static const int HC[4]   = {12544, 12544, 12544, 12368};  // agg_h node counts (<= NN)
    static const int A3C[4]  = {12544, 12544, 12544, 12416};  // agg3 spans (last covers pad to MPAD)

    // buffer plan (ping-pong; NO producer overwrites a buffer still being gathered):
    //   Y1 = buf1 (fp16), Y2 = buf2 (fp16), Y3 = buf1 (fp16; Y1 dead)
    //   Ahd = buf2 low region  (fp16, MPAD*256 halves; Y2 dead)
    //   T   = buf2 high region (f32 [NN,128]; offset NN*256 floats, disjoint from Ahd)
    __half* Y1 = (__half*)buf1;
    __half* Y2 = (__half*)buf2;
    __half* Y3 = (__half*)buf1;
    __half* Ahd = (__half*)buf2;
    float*  Thd = buf2 + (size_t)NN * 256;

    // ---- fork: branch B (s2) does CSR build + layer-2/3/head weight prep ----
    cudaEventRecord(evFork, 0);
    cudaStreamWaitEvent(s2, evFork, 0);

    convert_B_kernel<<<(512 * 512 + 255) / 256, 256, 0, s2>>>(W2, Bt2, 512);
    convert_B_kernel<<<(512 * 256 + 255) / 256, 256, 0, s2>>>(W3, Bt3, 256);
    pack_heads_kernel<<<(128 * 256 + 255) / 256, 256, 0, s2>>>(We, be, Wh, bh, Wg, bg);
    zero_indeg_kernel<<<(NN + 255) / 256, 256, 0, s2>>>();
    count_kernel<<<(NE + 255) / 256, 256, 0, s2>>>(dstArr);
    scan_part1<<<49, 1024, 0, s2>>>();
    scan_part2<<<1, 1, 0, s2>>>();
    scan_part3<<<49, 1024, 0, s2>>>();
    scatter_kernel<<<(NE + 255) / 256, 256, 0, s2>>>(srcArr, dstArr);
    cudaEventRecord(evCSR, s2);

    // ---- main (origin): x conversion + layer-1 weights + full layer-1 GEMM -> Y1 (buf1) ----
    convert_x_kernel<<<(MPAD * 128 + 255) / 256, 256>>>(x);
    convert_B_kernel<<<(512 * 512 + 255) / 256, 256>>>(W1, Bt1, 512);
    gemm_mma_kernel<512, 1, __half><<<dim3(4, 391), 256, GEMM_SMEM>>>(Ah, Bt1, Y1, NN, 512, 0);

    // ---- boundary 1: agg1 chunks read Y1(buf1) -> g_Ah; GEMM2 chunks -> Y2 (buf2) ----
    cudaStreamWaitEvent(0, evCSR, 0);
    for (int c = 0; c < 4; ++c) {
        aggregate_h_kernel<<<HC[c] / 4, 256>>>(Y1, b1, NB[c]);
        cudaEventRecord(aEv[c], 0);
    }
    for (int c = 0; c < 4; ++c) {
        cudaStreamWaitEvent(s2, aEv[c], 0);
        gemm_mma_kernel<512, 1, __half><<<dim3(4, CB[c]), 256, GEMM_SMEM, s2>>>(Ah, Bt2, Y2, NN, 512, NB[c]);
    }
    cudaEventRecord(evG2, s2);

    // ---- boundary 2: agg2 chunks read Y2(buf2) -> g_Ah; GEMM3 chunks -> Y3 (buf1, Y1 dead) ----
    cudaStreamWaitEvent(0, evG2, 0);
    for (int c = 0; c < 4; ++c) {
        aggregate_h_kernel<<<HC[c] / 4, 256>>>(Y2, b2, NB[c]);
        cudaEventRecord(bEv[c], 0);
    }
    for (int c = 0; c < 4; ++c) {
        cudaStreamWaitEvent(s2, bEv[c], 0);
        gemm_mma_kernel<512, 1, __half><<<dim3(2, CB[c]), 256, GEMM_SMEM, s2>>>(Ah, Bt3, Y3, NN, 256, NB[c]);
    }
    cudaEventRecord(evG3, s2);

    // ---- boundary 3: agg3 chunks read Y3(buf1) -> emb + Ahd(buf2 low); heads -> T (buf2 high) ----
    cudaStreamWaitEvent(0, evG3, 0);
    for (int c = 0; c < 4; ++c) {
        aggregate3_kernel<<<A3C[c] / 8, 256>>>(Y3, emb, b3, Ahd, NB[c]);
        cudaEventRecord(cEv[c], 0);
    }
    for (int c = 0; c < 4; ++c) {
        cudaStreamWaitEvent(s2, cEv[c], 0);
        gemm_mma_kernel<256, 2, float><<<dim3(1, CB[c]), 256, GEMM_SMEM, s2>>>(Ahd, Whd, Thd, NN, 128, NB[c]);
    }
    split_heads_kernel<<<(NN * 72 + 255) / 256, 256, 0, s2>>>(Thd, outE, outH, outG);
    cudaEventRecord(evTail, s2);

    // ---- join everything back to origin ----
    cudaStreamWaitEvent(0, evTail, 0);
}